// round 11
// baseline (speedup 1.0000x reference)
#include <cuda_runtime.h>
#include <math.h>

// NoisyTopKRouter eval-mode:
//   inputs:  x [4,8192,2048] f32, W_gate [2048,8] f32, W_noise (UNUSED), top_k=2
//   outputs (f32, concatenated in d_out):
//     dispatch_weights [N,2], top_k_idx [N,2] (as float), auxiliary_loss scalar
//
// Design: 256-thr block; warp w owns columns [w*256, w*256+256) with its weight
// slice in REGISTERS (zero weight traffic in steady state). x streams through a
// 4-stage cp.async.bulk (TMA) smem ring, 16 tiles x 2 rows (16 KB) per block.
// The copy engine owns DRAM latency; warps only do LDS + FFMA2 + SHFL.

#define D        2048
#define D4       512        // D / 4
#define NEXP     8
#define RPT      2          // rows per tile
#define NSTG     4          // ring stages
#define NT       16         // tiles per block
#define RPB      (RPT*NT)   // 32 rows per block
#define TBYTES   (RPT*D*4)  // 16 KB per tile
#define TF4      (RPT*D4)   // float4s per tile

__device__ float    g_load[NEXP];
__device__ float    g_imp[NEXP];
__device__ unsigned g_ctr;
// Rearranged W_gate (R8 layout): idx (((w*2+grp)*4+j)*2+half)*32 + lane
// for column c = w*256 + grp*128 + lane*4 + j; half0 = experts 0..3, half1 = 4..7.
__device__ float4   g_W2[8 * 2 * 4 * 2 * 32];   // 64 KB

__device__ __forceinline__ unsigned long long pack2(float x, float y) {
    unsigned long long r;
    asm("mov.b64 %0, {%1, %2};" : "=l"(r) : "f"(x), "f"(y));
    return r;
}
__device__ __forceinline__ void unpack2(unsigned long long v, float& x, float& y) {
    asm("mov.b64 {%0, %1}, %2;" : "=f"(x), "=f"(y) : "l"(v));
}
__device__ __forceinline__ void ffma2(unsigned long long& d,
                                      unsigned long long a, unsigned long long b) {
    asm("fma.rn.f32x2 %0, %1, %2, %0;" : "+l"(d) : "l"(a), "l"(b));
}
__device__ __forceinline__ unsigned long long add2(unsigned long long a,
                                                   unsigned long long b) {
    unsigned long long r;
    asm("add.rn.f32x2 %0, %1, %2;" : "=l"(r) : "l"(a), "l"(b));
    return r;
}
__device__ __forceinline__ void bulk_g2s(void* sdst, const void* gsrc,
                                         unsigned bytes, unsigned mbar) {
    unsigned d = (unsigned)__cvta_generic_to_shared(sdst);
    asm volatile(
        "cp.async.bulk.shared::cta.global.mbarrier::complete_tx::bytes [%0], [%1], %2, [%3];"
        :: "r"(d), "l"(gsrc), "r"(bytes), "r"(mbar) : "memory");
}
__device__ __forceinline__ void mbar_wait(unsigned mbar, unsigned ph) {
    unsigned done;
    do {
        asm volatile(
            "{\n\t.reg .pred p;\n\t"
            "mbarrier.try_wait.parity.acquire.cta.shared::cta.b64 p, [%1], %2, 0x989680;\n\t"
            "selp.b32 %0, 1, 0, p;\n\t}"
            : "=r"(done) : "r"(mbar), "r"(ph) : "memory");
    } while (!done);
}

// Rearrange W_gate + zero global accumulators.
__global__ void prep_kernel(const float* __restrict__ Wg) {
    const int c = blockIdx.x * 128 + threadIdx.x;            // column 0..2047
    const float4* Wg4 = (const float4*)Wg;
    const int w = c >> 8, rem = c & 255;
    const int grp = rem >> 7, l = (rem & 127) >> 2, j = rem & 3;
#pragma unroll
    for (int half = 0; half < 2; half++)
        g_W2[((((w * 2 + grp) * 4 + j) * 2) + half) * 32 + l] = Wg4[c * 2 + half];
    if (blockIdx.x == 0) {
        if (threadIdx.x < NEXP) { g_load[threadIdx.x] = 0.f; g_imp[threadIdx.x] = 0.f; }
        if (threadIdx.x == NEXP) g_ctr = 0u;
    }
}

__global__ __launch_bounds__(256, 2)
void router_main(const float* __restrict__ x,
                 float* __restrict__ out_w, float* __restrict__ out_idx,
                 float* __restrict__ out_aux) {
    extern __shared__ __align__(16) float4 s_x[];   // NSTG * TF4 float4 = 64 KB
    __shared__ float s_part[8][RPB][9];             // [warp][row][expert], padded
    __shared__ float s_load[NEXP];
    __shared__ float s_imp[NEXP];
    __shared__ unsigned s_ticket;
    __shared__ __align__(8) unsigned long long s_mbar[NSTG];

    const int tid  = threadIdx.x;
    const int warp = tid >> 5;
    const int lane = tid & 31;

    if (tid < NEXP) { s_load[tid] = 0.f; s_imp[tid] = 0.f; }
    if (tid == 0) {
#pragma unroll
        for (int s = 0; s < NSTG; s++) {
            unsigned mb = (unsigned)__cvta_generic_to_shared(&s_mbar[s]);
            asm volatile("mbarrier.init.shared.b64 [%0], %1;" :: "r"(mb), "r"(1));
        }
        asm volatile("fence.proxy.async.shared::cta;" ::: "memory");
    }
    __syncthreads();

    const int row0 = blockIdx.x * RPB;
    const float* gx = x + (size_t)row0 * D;

    // Prologue: fill all 4 stages.
    if (tid == 0) {
#pragma unroll
        for (int t = 0; t < NSTG; t++) {
            unsigned mb = (unsigned)__cvta_generic_to_shared(&s_mbar[t]);
            asm volatile("mbarrier.arrive.expect_tx.shared.b64 _, [%0], %1;"
                         :: "r"(mb), "r"((unsigned)TBYTES));
            bulk_g2s(s_x + t * TF4, gx + (size_t)t * RPT * D, TBYTES, mb);
        }
    }

    // ---- weights -> registers (overlaps with the in-flight copies) ----
    const ulonglong2* wq2 = (const ulonglong2*)g_W2;
    unsigned long long w0[16], w1[16];
#pragma unroll
    for (int grp = 0; grp < 2; grp++)
#pragma unroll
        for (int j = 0; j < 4; j++)
#pragma unroll
            for (int half = 0; half < 2; half++) {
                ulonglong2 v = __ldg(&wq2[((((warp * 2 + grp) * 4 + j) * 2) + half) * 32 + lane]);
                w0[grp * 8 + j * 2 + half] = v.x;
                w1[grp * 8 + j * 2 + half] = v.y;
            }

    const int base = warp * 64 + lane;   // float4 index of this lane's first col

#pragma unroll 1
    for (int t = 0; t < NT; t++) {
        const int s  = t & (NSTG - 1);
        const unsigned ph = (t >> 2) & 1;
        const unsigned mb = (unsigned)__cvta_generic_to_shared(&s_mbar[s]);
        mbar_wait(mb, ph);

        const float4* st = s_x + s * TF4;
        unsigned long long acc[RPT][4];
#pragma unroll
        for (int rr = 0; rr < RPT; rr++)
#pragma unroll
            for (int p = 0; p < 4; p++) acc[rr][p] = 0ull;

#pragma unroll
        for (int grp = 0; grp < 2; grp++) {
            float4 xv[RPT];
#pragma unroll
            for (int rr = 0; rr < RPT; rr++)
                xv[rr] = st[rr * D4 + base + grp * 32];
#pragma unroll
            for (int j = 0; j < 4; j++) {
                const int b = grp * 8 + j * 2;
#pragma unroll
                for (int rr = 0; rr < RPT; rr++) {
                    float xc = (j == 0) ? xv[rr].x : (j == 1) ? xv[rr].y
                             : (j == 2) ? xv[rr].z : xv[rr].w;
                    unsigned long long xb = pack2(xc, xc);
                    ffma2(acc[rr][0], xb, w0[b]);       // experts 0,1
                    ffma2(acc[rr][1], xb, w1[b]);       // experts 2,3
                    ffma2(acc[rr][2], xb, w0[b + 1]);   // experts 4,5
                    ffma2(acc[rr][3], xb, w1[b + 1]);   // experts 6,7
                }
            }
        }

        // All warps finished reading stage s -> refill it with tile t+4.
        __syncthreads();
        if (tid == 0 && t + NSTG < NT) {
            asm volatile("fence.proxy.async.shared::cta;" ::: "memory");
            asm volatile("mbarrier.arrive.expect_tx.shared.b64 _, [%0], %1;"
                         :: "r"(mb), "r"((unsigned)TBYTES));
            bulk_g2s(s_x + s * TF4, gx + (size_t)(t + NSTG) * RPT * D, TBYTES, mb);
        }

        // Batched butterflies (8 independent chains), then stash partials.
#pragma unroll
        for (int rr = 0; rr < RPT; rr++)
#pragma unroll
            for (int p = 0; p < 4; p++) {
#pragma unroll
                for (int off = 16; off > 0; off >>= 1)
                    acc[rr][p] = add2(acc[rr][p],
                                      __shfl_xor_sync(0xffffffffu, acc[rr][p], off));
            }

        if (lane < NEXP) {
#pragma unroll
            for (int rr = 0; rr < RPT; rr++) {
                float lo, hi;
                unpack2(acc[rr][lane >> 1], lo, hi);
                s_part[warp][t * RPT + rr][lane] = (lane & 1) ? hi : lo;
            }
        }
    }

    __syncthreads();

    // ---- epilogue: one thread per row (threads 0..31) ----
    if (tid < RPB) {
        const int r = tid, row = row0 + r;
        float h[NEXP];
#pragma unroll
        for (int e = 0; e < NEXP; e++) {
            float sum = 0.f;
#pragma unroll
            for (int w = 0; w < 8; w++) sum += s_part[w][r][e];
            h[e] = sum;
        }

        // top-2 (lowest index wins ties, matching jax.lax.top_k)
        int e0 = 0; float v0 = h[0];
#pragma unroll
        for (int e = 1; e < NEXP; e++)
            if (h[e] > v0) { v0 = h[e]; e0 = e; }
        int e1 = -1; float v1 = -3.4e38f;
#pragma unroll
        for (int e = 0; e < NEXP; e++)
            if (e != e0 && h[e] > v1) { v1 = h[e]; e1 = e; }

        float wg0 = 1.f / (1.f + expf(v1 - v0));
        float wg1 = 1.f - wg0;

        float p[NEXP]; float Z = 0.f;
#pragma unroll
        for (int e = 0; e < NEXP; e++) { p[e] = expf(h[e] - v0); Z += p[e]; }
        float invZ = 1.f / Z;
#pragma unroll
        for (int e = 0; e < NEXP; e++) atomicAdd(&s_imp[e], p[e] * invZ);
        atomicAdd(&s_load[e0], 1.f);
        atomicAdd(&s_load[e1], 1.f);

        out_w[row * 2]       = wg0;
        out_w[row * 2 + 1]   = wg1;
        out_idx[row * 2]     = (float)e0;
        out_idx[row * 2 + 1] = (float)e1;
    }

    __syncthreads();
    if (tid < NEXP) {
        atomicAdd(&g_load[tid], s_load[tid]);
        atomicAdd(&g_imp[tid],  s_imp[tid]);
        __threadfence();
    }
    __syncthreads();
    if (tid == 0) s_ticket = atomicAdd(&g_ctr, 1u);
    __syncthreads();

    // Last block computes the auxiliary loss.
    if (s_ticket == gridDim.x - 1 && tid == 0) {
        volatile float* vl_ = g_load;
        volatile float* vi_ = g_imp;
        float l[NEXP], im[NEXP];
        float ml = 0.f, mi = 0.f;
#pragma unroll
        for (int e = 0; e < NEXP; e++) {
            l[e] = vl_[e]; im[e] = vi_[e];
            ml += l[e];    mi += im[e];
        }
        ml *= (1.f / NEXP);
        mi *= (1.f / NEXP);
        float vl = 0.f, vi = 0.f;
#pragma unroll
        for (int e = 0; e < NEXP; e++) {
            float dl = l[e]  - ml; vl += dl * dl;
            float di = im[e] - mi; vi += di * di;
        }
        vl *= (1.f / (NEXP - 1));   // ddof = 1
        vi *= (1.f / (NEXP - 1));
        float cv = sqrtf(vl) / (ml + 1e-6f) + sqrtf(vi) / (mi + 1e-6f);
        *out_aux = cv * 0.01f;
    }
}

extern "C" void kernel_launch(void* const* d_in, const int* in_sizes, int n_in,
                              void* d_out, int out_size) {
    const float* x  = (const float*)d_in[0];   // [4,8192,2048]
    const float* Wg = (const float*)d_in[1];   // [2048,8]
    // d_in[2] = W_noise (unused in eval), d_in[3] = top_k (=2)

    const int N = in_sizes[0] / D;             // 32768 rows

    float* out     = (float*)d_out;
    float* out_w   = out;                      // [N,2]
    float* out_idx = out + (size_t)N * 2;      // [N,2]
    float* out_aux = out + (size_t)N * 4;      // scalar

    const int dsmem = NSTG * TBYTES;           // 64 KB ring
    static int attr_set = -1;
    if (attr_set < 0) {
        cudaFuncSetAttribute(router_main,
                             cudaFuncAttributeMaxDynamicSharedMemorySize, dsmem);
        attr_set = 1;
    }

    prep_kernel<<<16, 128>>>(Wg);
    router_main<<<N / RPB, 256, dsmem>>>(x, out_w, out_idx, out_aux);
}